// round 10
// baseline (speedup 1.0000x reference)
#include <cuda_runtime.h>
#include <cuda_fp16.h>
#include <cstdint>

#define MCN     50000
#define PATHS   100000
#define TSTEPS  180
#define NOPT    32
#define BDIM    128
#define TILE    64
#define NT      1563         /* ceil(100000/64) */
#define HSTEP   (1.0f/360.0f)
#define RATEC   0.025f

__device__ float g_part[NT * NOPT];

// ---- shared memory byte offsets ----
#define OFF_SV   0            // 64 float2 = 512
#define OFF_OSM  512          // 4*64 f = 1024
#define OFF_BW   1536         // 128 float4 = 2048 ({b2,b2,Wo,Wo} pairs)
#define OFF_BO   3584         // 4 f
#define OFF_STRK 3600         // 32 f
#define OFF_MASK 3728         // 180 u32 = 720
#define OFF_WSUM 4448         // 32*4 f = 512
#define OFF_BSM  4960         // kk=2,3 B-frags: 4*2*8*32 uint2 = 16384
#define SMEM_TOTAL (OFF_BSM + 16384)

__device__ __forceinline__ uint32_t f2tf32(float f) {
    uint32_t u; asm("cvt.rna.tf32.f32 %0, %1;" : "=r"(u) : "f"(f)); return u;
}
__device__ __forceinline__ uint32_t packh2(float lo, float hi) {
    __half2 h = __floats2half2_rn(lo, hi);
    return *(uint32_t*)&h;
}
__device__ __forceinline__ void mma_f16(float c[4], const uint32_t a[4], uint32_t b0, uint32_t b1) {
    asm volatile("mma.sync.aligned.m16n8k16.row.col.f32.f16.f16.f32 "
                 "{%0,%1,%2,%3}, {%4,%5,%6,%7}, {%8,%9}, {%0,%1,%2,%3};"
                 : "+f"(c[0]), "+f"(c[1]), "+f"(c[2]), "+f"(c[3])
                 : "r"(a[0]), "r"(a[1]), "r"(a[2]), "r"(a[3]), "r"(b0), "r"(b1));
}
__device__ __forceinline__ void mma_tf32_k8(float c[4], uint32_t a0, uint32_t a1,
                                            uint32_t a2, uint32_t a3,
                                            uint32_t b0, uint32_t b1) {
    asm volatile("mma.sync.aligned.m16n8k8.row.col.f32.tf32.tf32.f32 "
                 "{%0,%1,%2,%3}, {%4,%5,%6,%7}, {%8,%9}, {%0,%1,%2,%3};"
                 : "+f"(c[0]), "+f"(c[1]), "+f"(c[2]), "+f"(c[3])
                 : "r"(a0), "r"(a1), "r"(a2), "r"(a3), "r"(b0), "r"(b1));
}

__global__ __launch_bounds__(BDIM, 5)
void sde_mc_hmma_kernel(const float* __restrict__ x,
                        const float* __restrict__ z,
                        const float* __restrict__ z1,
                        const float* __restrict__ W1,
                        const float* __restrict__ b1,
                        const float* __restrict__ W2,
                        const float* __restrict__ b2,
                        const float* __restrict__ Wo,
                        const float* __restrict__ bo)
{
    extern __shared__ char sm[];
    const int tid  = threadIdx.x;
    const int wid  = tid >> 5;       // warp = net
    const int lane = tid & 31;
    const int g    = lane >> 2;      // fragment group row
    const int t4   = lane & 3;       // fragment thread-in-group

    float2* SVs  = (float2*)(sm + OFF_SV);
    float*  osm  = (float*)(sm + OFF_OSM);
    float4* bw4S = (float4*)(sm + OFF_BW);
    float*  boS  = (float*)(sm + OFF_BO);
    float*  strk = (float*)(sm + OFF_STRK);
    unsigned* maskS = (unsigned*)(sm + OFF_MASK);
    float*  wsum = (float*)(sm + OFF_WSUM);
    uint2*  bsm  = (uint2*)(sm + OFF_BSM);

    // ---- stage small params ----
    {
        int netI = tid >> 5, rem = tid & 31, j4 = rem >> 2, t4i = rem & 3;
        int c = netI * 64 + j4 * 8 + 2 * t4i;
        bw4S[tid] = make_float4(__ldg(b2 + c), __ldg(b2 + c + 1),
                                __ldg(Wo + c), __ldg(Wo + c + 1));
    }
    if (tid < 4)    boS[tid]  = bo[tid];
    if (tid < NOPT) strk[tid] = x[2 * tid + 1];
    for (int i = tid; i < TSTEPS; i += BDIM) {
        unsigned m = 0;
        for (int k = 0; k < NOPT; k++)
            if ((int)x[2 * k] == i + 1) m |= (1u << k);
        maskS[i] = m;
    }
    if (tid < NOPT * 4) wsum[tid] = 0.0f;
    if (tid < TILE) SVs[tid] = make_float2(100.0f, 0.04f);

    // ---- stage kk=2,3 B-fragments to smem (conflict-free fragment-native) ----
    // bsm[((netI*2+kkh)*8+nn)*32 + lane] = {h2(W[n][k],W[n][k+1]), h2(W[n][k+8],W[n][k+9])}
    for (int e = tid; e < 4 * 2 * 8 * 32; e += BDIM) {
        int ln  = e & 31, nn = (e >> 5) & 7, kkh = (e >> 8) & 1, netI = e >> 9;
        int n = nn * 8 + (ln >> 2);
        int k = (kkh + 2) * 16 + 2 * (ln & 3);
        const float* Wn = W2 + netI * 4096 + n * 64;
        bsm[e] = make_uint2(packh2(__ldg(Wn + k),     __ldg(Wn + k + 1)),
                            packh2(__ldg(Wn + k + 8), __ldg(Wn + k + 9)));
    }

    // ---- register-resident fp16 B fragments for kk=0,1: warp's net = wid ----
    const int net = wid;
    uint32_t breg[2][8][2];
    {
        const float* Wn = W2 + net * 4096;
        #pragma unroll
        for (int kk = 0; kk < 2; kk++)
            #pragma unroll
            for (int nn = 0; nn < 8; nn++) {
                int n = nn * 8 + g;
                int k = kk * 16 + 2 * t4;
                breg[kk][nn][0] = packh2(__ldg(Wn + n * 64 + k),     __ldg(Wn + n * 64 + k + 1));
                breg[kk][nn][1] = packh2(__ldg(Wn + n * 64 + k + 8), __ldg(Wn + n * 64 + k + 9));
            }
    }
    // ---- layer-1 tf32 B fragments (rate+b1 folded into bias col) ----
    uint32_t w1b0[8], w1b1[8];
    {
        const float* W1n = W1 + net * 256;
        const float* b1n = b1 + net * 64;
        #pragma unroll
        for (int j = 0; j < 8; j++) {
            int n = j * 8 + g;
            w1b0[j] = (t4 < 3) ? f2tf32(__ldg(W1n + n * 4 + t4)) : 0u;
            w1b1[j] = (t4 == 0)
                    ? f2tf32(fmaf(RATEC, __ldg(W1n + n * 4 + 3), __ldg(b1n + n)))
                    : 0u;
        }
    }
    const uint32_t a2c = (t4 == 0) ? 0x3F800000u : 0u;   // X bias col = 1.0

    // ---- ownership: warp w owns paths [16w,16w+16), lanes 0..15 ----
    const int  pown  = wid * 16 + (lane & 15);
    const bool owner = (lane < 16);
    const int  pg    = blockIdx.x * TILE + pown;
    const bool valid = owner && (pg < PATHS);
    const int  zrow  = (pg < MCN) ? pg : (pg < PATHS ? pg - MCN : 0);
    const float sgn  = (pg < MCN) ? 1.0f : -1.0f;
    const float* zr  = z  + (long)zrow * TSTEPS;
    const float* z1r = z1 + (long)zrow * TSTEPS;
    const float SQH  = sqrtf(HSTEP);
    const float SQ75 = 0.8660254037844386f;

    float S = 100.0f, V = 0.04f;

    const uint2* bsmN = bsm + (net * 2) * 8 * 32 + lane;

    for (int i = 0; i < TSTEPS; i++) {
        __syncthreads();   // SVs from previous step (and init staging) visible

        float za = 0.0f, zb = 0.0f;
        if (owner) { za = __ldg(zr + i); zb = __ldg(z1r + i); }

        const uint32_t tc = f2tf32((float)i * HSTEP);

        // ---- fused layer1(tf32 MMA) -> layer2(fp16 MMA) -> epilogue; warp = net ----
        #pragma unroll
        for (int m = 0; m < 4; m++) {
            const int row0 = m * 16;
            float2 sv0 = SVs[row0 + g];
            float2 sv1 = SVs[row0 + g + 8];
            uint32_t s0 = f2tf32(sv0.x), v0 = f2tf32(sv0.y);
            uint32_t s1 = f2tf32(sv1.x), v1 = f2tf32(sv1.y);
            uint32_t a0 = (t4 == 0) ? tc : (t4 == 1) ? s0 : (t4 == 2) ? v0 : 0u;
            uint32_t a1 = (t4 == 0) ? tc : (t4 == 1) ? s1 : (t4 == 2) ? v1 : 0u;

            // layer 1 -> A fragments (relu+pack in regs)
            uint32_t a[4][4];
            #pragma unroll
            for (int kk = 0; kk < 4; kk++) {
                #pragma unroll
                for (int jh = 0; jh < 2; jh++) {
                    int j = 2 * kk + jh;
                    float d[4] = {0.f, 0.f, 0.f, 0.f};
                    mma_tf32_k8(d, a0, a1, a2c, a2c, w1b0[j], w1b1[j]);
                    a[kk][2 * jh]     = packh2(fmaxf(d[0], 0.f), fmaxf(d[1], 0.f));
                    a[kk][2 * jh + 1] = packh2(fmaxf(d[2], 0.f), fmaxf(d[3], 0.f));
                }
            }

            // layer 2 + epilogue: kk 0,1 from regs; kk 2,3 from smem frags
            float op0 = 0.f, op1 = 0.f;
            #pragma unroll
            for (int nh = 0; nh < 2; nh++) {
                #pragma unroll
                for (int nj = 0; nj < 4; nj++) {
                    const int nn = nh * 4 + nj;
                    float4 bw = bw4S[net * 32 + nn * 4 + t4];
                    float acc[4] = {bw.x, bw.y, bw.x, bw.y};
                    mma_f16(acc, a[0], breg[0][nn][0], breg[0][nn][1]);
                    mma_f16(acc, a[1], breg[1][nn][0], breg[1][nn][1]);
                    uint2 bs2 = bsmN[nn * 32];
                    mma_f16(acc, a[2], bs2.x, bs2.y);
                    uint2 bs3 = bsmN[(8 + nn) * 32];
                    mma_f16(acc, a[3], bs3.x, bs3.y);
                    float q0 = fmaxf(acc[0], 0.f);
                    float q1 = fmaxf(acc[1], 0.f);
                    float q2 = fmaxf(acc[2], 0.f);
                    float q3 = fmaxf(acc[3], 0.f);
                    op0 = fmaf(bw.z, q0, fmaf(bw.w, q1, op0));
                    op1 = fmaf(bw.z, q2, fmaf(bw.w, q3, op1));
                }
            }
            op0 += __shfl_xor_sync(0xffffffffu, op0, 1);
            op0 += __shfl_xor_sync(0xffffffffu, op0, 2);
            op1 += __shfl_xor_sync(0xffffffffu, op1, 1);
            op1 += __shfl_xor_sync(0xffffffffu, op1, 2);
            if (t4 == 0) {
                osm[net * TILE + row0 + g]     = op0;
                osm[net * TILE + row0 + 8 + g] = op1;
            }
        }
        __syncthreads();   // osm ready

        // ---- Euler update + payoff: ALL warps, 16 lanes each ----
        if (owner) {
            float o0 = osm[0 * TILE + pown] + boS[0];
            float o1 = osm[1 * TILE + pown] + boS[1];
            float o2 = osm[2 * TILE + pown] + boS[2];
            float o3 = osm[3 * TILE + pown] + boS[3];
            float z1c = fmaf(SQ75, zb, -0.5f * za);
            float dW  = SQH * sgn * za;
            float dW1 = SQH * sgn * z1c;
            S = fmaxf(fmaf(o1, dW,  fmaf(o0, HSTEP, S)), 0.0f);
            V = fmaxf(fmaf(o3, dW1, fmaf(o2, HSTEP, V)), 0.0f);
            SVs[pown] = make_float2(S, V);
        }
        {
            unsigned m = maskS[i];
            while (m) {
                int k = __ffs(m) - 1; m &= m - 1;
                float pay = valid ? fmaxf(S - strk[k], 0.0f) : 0.0f;
                #pragma unroll
                for (int off = 8; off; off >>= 1)
                    pay += __shfl_down_sync(0xffffffffu, pay, off);
                if (lane == 0) wsum[k * 4 + wid] = pay;
            }
        }
    }

    __syncthreads();
    if (tid < NOPT) {
        float s = wsum[tid * 4] + wsum[tid * 4 + 1]
                + wsum[tid * 4 + 2] + wsum[tid * 4 + 3];
        g_part[blockIdx.x * NOPT + tid] = s;
    }
}

// ---------------- finalize: one warp per option ----------------
__global__ void finalize_kernel(const float* __restrict__ x, float* __restrict__ out)
{
    int k = threadIdx.x >> 5, lane = threadIdx.x & 31;
    float s = 0.0f;
    for (int t = lane; t < NT; t += 32) s += g_part[t * NOPT + k];
    #pragma unroll
    for (int off = 16; off; off >>= 1) s += __shfl_down_sync(0xffffffffu, s, off);
    if (lane == 0)
        out[k] = (s * (1.0f / (2.0f * (float)MCN))) * expf(-RATEC * x[2 * k] / 360.0f);
}

__global__ void dummy_kernel() {}

extern "C" void kernel_launch(void* const* d_in, const int* in_sizes, int n_in,
                              void* d_out, int out_size)
{
    (void)in_sizes; (void)n_in; (void)out_size;
    const float* x  = (const float*)d_in[0];
    const float* z  = (const float*)d_in[1];
    const float* z1 = (const float*)d_in[2];
    const float* W1 = (const float*)d_in[3];
    const float* b1 = (const float*)d_in[4];
    const float* W2 = (const float*)d_in[5];
    const float* b2 = (const float*)d_in[6];
    const float* Wo = (const float*)d_in[7];
    const float* bo = (const float*)d_in[8];

    cudaFuncSetAttribute(sde_mc_hmma_kernel,
                         cudaFuncAttributeMaxDynamicSharedMemorySize, SMEM_TOTAL);
    dummy_kernel<<<1, 32>>>();
    dummy_kernel<<<1, 32>>>();
    dummy_kernel<<<1, 32>>>();
    sde_mc_hmma_kernel<<<NT, BDIM, SMEM_TOTAL>>>(x, z, z1, W1, b1, W2, b2, Wo, bo);
    finalize_kernel<<<1, 1024>>>(x, (float*)d_out);
}

// round 13
// speedup vs baseline: 1.1317x; 1.1317x over previous
#include <cuda_runtime.h>
#include <cuda_fp16.h>
#include <cstdint>

#define MCN     50000
#define PATHS   100000
#define TSTEPS  180
#define NOPT    32
#define BDIM    256
#define NT      782          /* ceil(100000/128) */
#define HSTEP   (1.0f/360.0f)
#define RATEC   0.025f

__device__ float g_part[NT * NOPT];

// ---- shared memory byte offsets ----
#define OFF_SV   0            // 128 float2 = 1024
#define OFF_OSM  1024         // 4*128 f = 2048
#define OFF_BW   3072         // 128 float4 = 2048 ({b2,b2,Wo,Wo} pairs)
#define OFF_BO   5120         // 4 f
#define OFF_STRK 5136         // 32 f
#define OFF_MASK 5264         // 180 u32 = 720
#define OFF_WSUM 5984         // 32*4 f = 512
#define SMEM_TOTAL 6512

__device__ __forceinline__ uint32_t packh2(float lo, float hi) {
    __half2 h = __floats2half2_rn(lo, hi);
    return *(uint32_t*)&h;
}
__device__ __forceinline__ uint32_t hmax2z(uint32_t u) {
    __half2 zero = __float2half2_rn(0.0f);
    __half2 r = __hmax2(*(__half2*)&u, zero);
    return *(uint32_t*)&r;
}
__device__ __forceinline__ void mma_f16_k16(float c[4], const uint32_t a[4],
                                            uint32_t b0, uint32_t b1) {
    asm volatile("mma.sync.aligned.m16n8k16.row.col.f32.f16.f16.f32 "
                 "{%0,%1,%2,%3}, {%4,%5,%6,%7}, {%8,%9}, {%0,%1,%2,%3};"
                 : "+f"(c[0]), "+f"(c[1]), "+f"(c[2]), "+f"(c[3])
                 : "r"(a[0]), "r"(a[1]), "r"(a[2]), "r"(a[3]), "r"(b0), "r"(b1));
}
__device__ __forceinline__ void mma_f16_k8(float c[4], uint32_t a0, uint32_t a1,
                                           uint32_t b0) {
    asm volatile("mma.sync.aligned.m16n8k8.row.col.f32.f16.f16.f32 "
                 "{%0,%1,%2,%3}, {%4,%5}, {%6}, {%0,%1,%2,%3};"
                 : "+f"(c[0]), "+f"(c[1]), "+f"(c[2]), "+f"(c[3])
                 : "r"(a0), "r"(a1), "r"(b0));
}

__global__ __launch_bounds__(BDIM, 2)
void sde_mc_hmma_kernel(const float* __restrict__ x,
                        const float* __restrict__ z,
                        const float* __restrict__ z1,
                        const float* __restrict__ W1,
                        const float* __restrict__ b1,
                        const float* __restrict__ W2,
                        const float* __restrict__ b2,
                        const float* __restrict__ Wo,
                        const float* __restrict__ bo)
{
    extern __shared__ char sm[];
    const int tid  = threadIdx.x;
    const int wid  = tid >> 5;
    const int lane = tid & 31;
    const int g    = lane >> 2;      // fragment group row
    const int t4   = lane & 3;       // fragment thread-in-group

    float2* SVs  = (float2*)(sm + OFF_SV);
    float*  osm  = (float*)(sm + OFF_OSM);
    float4* bw4S = (float4*)(sm + OFF_BW);
    float*  boS  = (float*)(sm + OFF_BO);
    float*  strk = (float*)(sm + OFF_STRK);
    unsigned* maskS = (unsigned*)(sm + OFF_MASK);
    float*  wsum = (float*)(sm + OFF_WSUM);

    // ---- stage small params ----
    // bw4[net*32 + nn*4 + t4i] = {b2[c], b2[c+1], Wo[c], Wo[c+1]}, c = net*64+nn*8+2*t4i
    if (tid < 128) {
        int netI = tid >> 5, rem = tid & 31, nn = rem >> 2, t4i = rem & 3;
        int c = netI * 64 + nn * 8 + 2 * t4i;
        bw4S[tid] = make_float4(__ldg(b2 + c), __ldg(b2 + c + 1),
                                __ldg(Wo + c), __ldg(Wo + c + 1));
    }
    if (tid < 4)    boS[tid]  = bo[tid];
    if (tid < NOPT) strk[tid] = x[2 * tid + 1];
    for (int i = tid; i < TSTEPS; i += BDIM) {
        unsigned m = 0;
        for (int k = 0; k < NOPT; k++)
            if ((int)x[2 * k] == i + 1) m |= (1u << k);
        maskS[i] = m;
    }
    if (tid < NOPT * 4) wsum[tid] = 0.0f;
    if (tid < 128) SVs[tid] = make_float2(100.0f, 0.04f);

    // ---- register-resident fp16 B fragments for layer 2: warp net = wid&3 ----
    const int net = wid & 3;
    uint32_t breg[4][8][2];
    {
        const float* Wn = W2 + net * 4096;
        #pragma unroll
        for (int kk = 0; kk < 4; kk++)
            #pragma unroll
            for (int nn = 0; nn < 8; nn++) {
                int n = nn * 8 + g;
                int k = kk * 16 + 2 * t4;
                breg[kk][nn][0] = packh2(__ldg(Wn + n * 64 + k),     __ldg(Wn + n * 64 + k + 1));
                breg[kk][nn][1] = packh2(__ldg(Wn + n * 64 + k + 8), __ldg(Wn + n * 64 + k + 9));
            }
    }
    // ---- layer-1 fp16 B fragments (m16n8k8): single reg per n-tile ----
    // Padded W1p[k][n]: k0=W1t, k1=W1s, k2=W1v, k3=0, k4=b1+rate*W1r, k5..7=0
    // b0 = {W1p[2*t4][n], W1p[2*t4+1][n]}
    uint32_t w1h[8];
    {
        const float* W1n = W1 + net * 256;
        const float* b1n = b1 + net * 64;
        #pragma unroll
        for (int j = 0; j < 8; j++) {
            int n = j * 8 + g;
            float lo, hi;
            if (t4 == 0)      { lo = __ldg(W1n + n * 4 + 0); hi = __ldg(W1n + n * 4 + 1); }
            else if (t4 == 1) { lo = __ldg(W1n + n * 4 + 2); hi = 0.0f; }
            else if (t4 == 2) { lo = fmaf(RATEC, __ldg(W1n + n * 4 + 3), __ldg(b1n + n)); hi = 0.0f; }
            else              { lo = 0.0f; hi = 0.0f; }
            w1h[j] = packh2(lo, hi);
        }
    }

    // ---- per-path state (threads 0..127 own paths) ----
    const int  pg    = blockIdx.x * 128 + (tid & 127);
    const bool owner = tid < 128;
    const bool valid = owner && (pg < PATHS);
    const int  zrow  = (pg < MCN) ? pg : (pg < PATHS ? pg - MCN : 0);
    const float sgn  = (pg < MCN) ? 1.0f : -1.0f;
    const float* zr  = z  + (long)zrow * TSTEPS;
    const float* z1r = z1 + (long)zrow * TSTEPS;
    const float SQH  = sqrtf(HSTEP);
    const float SQ75 = 0.8660254037844386f;

    float S = 100.0f, V = 0.04f;

    const int p  = tid & 127;
    const int mh = wid >> 2;     // row-half for GEMM
    const uint32_t one_h = 0x00003C00u;   // packh2(1.0, 0.0) — bias column

    for (int i = 0; i < TSTEPS; i++) {
        __syncthreads();   // SVs from previous step visible

        float za = 0.0f, zb = 0.0f;
        if (owner) { za = __ldg(zr + i); zb = __ldg(z1r + i); }

        const float th = (float)i * HSTEP;

        // ---- fused layer1(fp16 k8 MMA) -> layer2(fp16 k16 MMA) -> epilogue ----
        #pragma unroll
        for (int m = 0; m < 4; m++) {
            const int row0 = (mh * 4 + m) * 16;
            float2 sv0 = SVs[row0 + g];
            float2 sv1 = SVs[row0 + g + 8];
            // X row = [t, S, V, 0, 1, 0, 0, 0]; a0 = cols {2t4,2t4+1} of row g
            uint32_t a0 = (t4 == 0) ? packh2(th, sv0.x)
                        : (t4 == 1) ? packh2(sv0.y, 0.0f)
                        : (t4 == 2) ? one_h : 0u;
            uint32_t a1 = (t4 == 0) ? packh2(th, sv1.x)
                        : (t4 == 1) ? packh2(sv1.y, 0.0f)
                        : (t4 == 2) ? one_h : 0u;

            // layer 1 -> A fragments (pack then relu via hmax2)
            uint32_t a[4][4];
            #pragma unroll
            for (int kk = 0; kk < 4; kk++) {
                #pragma unroll
                for (int jh = 0; jh < 2; jh++) {
                    int j = 2 * kk + jh;
                    float d[4] = {0.f, 0.f, 0.f, 0.f};
                    mma_f16_k8(d, a0, a1, w1h[j]);
                    a[kk][2 * jh]     = hmax2z(packh2(d[0], d[1]));
                    a[kk][2 * jh + 1] = hmax2z(packh2(d[2], d[3]));
                }
            }

            // layer 2 + epilogue (acc seeded with b2; fused b2/Wo LDS.128)
            float op0 = 0.f, op1 = 0.f;
            #pragma unroll
            for (int nh = 0; nh < 2; nh++) {
                #pragma unroll
                for (int nj = 0; nj < 4; nj++) {
                    const int nn = nh * 4 + nj;
                    float4 bw = bw4S[net * 32 + nn * 4 + t4];
                    float acc[4] = {bw.x, bw.y, bw.x, bw.y};
                    #pragma unroll
                    for (int kk = 0; kk < 4; kk++)
                        mma_f16_k16(acc, a[kk], breg[kk][nn][0], breg[kk][nn][1]);
                    float q0 = fmaxf(acc[0], 0.f);
                    float q1 = fmaxf(acc[1], 0.f);
                    float q2 = fmaxf(acc[2], 0.f);
                    float q3 = fmaxf(acc[3], 0.f);
                    op0 = fmaf(bw.z, q0, fmaf(bw.w, q1, op0));
                    op1 = fmaf(bw.z, q2, fmaf(bw.w, q3, op1));
                }
            }
            op0 += __shfl_xor_sync(0xffffffffu, op0, 1);
            op0 += __shfl_xor_sync(0xffffffffu, op0, 2);
            op1 += __shfl_xor_sync(0xffffffffu, op1, 1);
            op1 += __shfl_xor_sync(0xffffffffu, op1, 2);
            if (t4 == 0) {
                osm[net * 128 + row0 + g]     = op0;
                osm[net * 128 + row0 + 8 + g] = op1;
            }
        }
        __syncthreads();   // osm ready

        // ---- Euler update + payoff (owners) ----
        if (owner) {
            float o0 = osm[0 * 128 + p] + boS[0];
            float o1 = osm[1 * 128 + p] + boS[1];
            float o2 = osm[2 * 128 + p] + boS[2];
            float o3 = osm[3 * 128 + p] + boS[3];
            float z1c = fmaf(SQ75, zb, -0.5f * za);
            float dW  = SQH * sgn * za;
            float dW1 = SQH * sgn * z1c;
            S = fmaxf(fmaf(o1, dW,  fmaf(o0, HSTEP, S)), 0.0f);
            V = fmaxf(fmaf(o3, dW1, fmaf(o2, HSTEP, V)), 0.0f);
            SVs[p] = make_float2(S, V);

            unsigned m = maskS[i];
            while (m) {
                int k = __ffs(m) - 1; m &= m - 1;
                float pay = valid ? fmaxf(S - strk[k], 0.0f) : 0.0f;
                #pragma unroll
                for (int off = 16; off; off >>= 1)
                    pay += __shfl_down_sync(0xffffffffu, pay, off);
                if (lane == 0) wsum[k * 4 + wid] = pay;
            }
        }
    }

    __syncthreads();
    if (tid < NOPT) {
        float s = wsum[tid * 4] + wsum[tid * 4 + 1]
                + wsum[tid * 4 + 2] + wsum[tid * 4 + 3];
        g_part[blockIdx.x * NOPT + tid] = s;
    }
}

// ---------------- finalize: one warp per option ----------------
__global__ void finalize_kernel(const float* __restrict__ x, float* __restrict__ out)
{
    int k = threadIdx.x >> 5, lane = threadIdx.x & 31;
    float s = 0.0f;
    for (int t = lane; t < NT; t += 32) s += g_part[t * NOPT + k];
    #pragma unroll
    for (int off = 16; off; off >>= 1) s += __shfl_down_sync(0xffffffffu, s, off);
    if (lane == 0)
        out[k] = (s * (1.0f / (2.0f * (float)MCN))) * expf(-RATEC * x[2 * k] / 360.0f);
}

__global__ void dummy_kernel() {}

extern "C" void kernel_launch(void* const* d_in, const int* in_sizes, int n_in,
                              void* d_out, int out_size)
{
    (void)in_sizes; (void)n_in; (void)out_size;
    const float* x  = (const float*)d_in[0];
    const float* z  = (const float*)d_in[1];
    const float* z1 = (const float*)d_in[2];
    const float* W1 = (const float*)d_in[3];
    const float* b1 = (const float*)d_in[4];
    const float* W2 = (const float*)d_in[5];
    const float* b2 = (const float*)d_in[6];
    const float* Wo = (const float*)d_in[7];
    const float* bo = (const float*)d_in[8];

    cudaFuncSetAttribute(sde_mc_hmma_kernel,
                         cudaFuncAttributeMaxDynamicSharedMemorySize, SMEM_TOTAL);
    dummy_kernel<<<1, 32>>>();
    dummy_kernel<<<1, 32>>>();
    dummy_kernel<<<1, 32>>>();
    sde_mc_hmma_kernel<<<NT, BDIM, SMEM_TOTAL>>>(x, z, z1, W1, b1, W2, b2, Wo, bo);
    finalize_kernel<<<1, 1024>>>(x, (float*)d_out);
}